// round 7
// baseline (speedup 1.0000x reference)
#include <cuda_runtime.h>
#include <cuda_bf16.h>

#define O_CH  256
#define C_IN  128
#define KH_N  24
#define N_IN  24
#define N_OUT 24
#define KS    5
#define VOL   (KS*KS*KS)                          // 125
#define WH_SIZE ((size_t)O_CH*N_IN*C_IN*N_OUT)    // 18,874,368
#define A_GRP 6                                   // a's per gather block
#define NB_WH (O_CH * (N_IN / A_GRP))             // 1024 gather blocks
#define NB_RN O_CH                                // 256 wrn blocks
#define APITCH (C_IN * N_OUT)                     // 3072 floats per (o,a)

// ---------------------------------------------------------------------------
// Single fused kernel.
// Gather blocks: (o, 6 a's). Stage weight_H[o] in smem, compute nn inline,
// preload each thread's 3 periodic nn indices per a into registers, then
// emit fully-coalesced 128B-aligned stores: out[e] = sw[(e/24)*24 + nn[a,e%24]].
// ---------------------------------------------------------------------------
__global__ void __launch_bounds__(256) fused_kernel(
        const float* __restrict__ in_H,      // [24,3,3]
        const float* __restrict__ out_H,     // [24,3,3]
        const float* __restrict__ grid_H,    // [24,3,3]
        const float* __restrict__ grid_Rn,   // [3,5,5,5]
        const float* __restrict__ weight_H,  // [256,128,24]
        const float* __restrict__ weight_Rn, // [256,1,5,5,5]
        float* __restrict__ out) {
    const int idx = blockIdx.x;
    const int t = threadIdx.x;

    if (idx < NB_WH) {
        // ================= wH gather =================
        __shared__ float sw[C_IN * KH_N];        // 12 KB weights
        __shared__ float sOH[216], sGH[216], sIH[A_GRP * 9];
        __shared__ int   snn[A_GRP * N_OUT];     // 144 indices

        const int o  = idx / (N_IN / A_GRP);
        const int a0 = (idx % (N_IN / A_GRP)) * A_GRP;

        const float4* wsrc = reinterpret_cast<const float4*>(
            weight_H + (size_t)o * C_IN * KH_N);
#pragma unroll
        for (int j = t; j < 768; j += 256)
            reinterpret_cast<float4*>(sw)[j] = wsrc[j];
        if (t < 216) { sOH[t] = out_H[t]; sGH[t] = grid_H[t]; }
        if (t < A_GRP * 9) sIH[t] = in_H[a0 * 9 + t];
        __syncthreads();

        // inline nn argmax: thread t<144 handles (a = a0 + t/24, b = t%24)
        if (t < A_GRP * N_OUT) {
            const int al = t / N_OUT, b = t % N_OUT;
            float P[9];
#pragma unroll
            for (int i = 0; i < 3; i++)
#pragma unroll
                for (int j = 0; j < 3; j++) {
                    float s = 0.f;
#pragma unroll
                    for (int k = 0; k < 3; k++)
                        s += sOH[b * 9 + k * 3 + i] * sIH[al * 9 + k * 3 + j];
                    P[i * 3 + j] = s;
                }
            float best = -1e30f; int bi = 0;
            for (int kh = 0; kh < KH_N; kh++) {
                float s = 0.f;
#pragma unroll
                for (int i = 0; i < 9; i++) s += P[i] * sGH[kh * 9 + i];
                if (s > best) { best = s; bi = kh; }   // strict > = first max
            }
            snn[t] = bi;
        }
        __syncthreads();

        // preload periodic nn indices: e = 256*i + t  ->  e%24 = (t+16*(i%3))%24
        int nnr[A_GRP][3];
#pragma unroll
        for (int r = 0; r < 3; r++) {
            const int b = (t + 16 * r) % 24;
#pragma unroll
            for (int al = 0; al < A_GRP; al++)
                nnr[al][r] = snn[al * N_OUT + b];
        }

        float* dsta = out + ((size_t)o * N_IN + a0) * APITCH;
#pragma unroll
        for (int i = 0; i < 12; i++) {
            const int e = 256 * i + t;
            const int c = e / 24;
            const int r = i % 3;
            const float* swr = sw + c * KH_N;
#pragma unroll
            for (int al = 0; al < A_GRP; al++)
                dsta[al * APITCH + e] = swr[nnr[al][r]];
        }
    } else {
        // ================= wRn trilinear =================
        __shared__ float vol[VOL];
        __shared__ float R[216];
        __shared__ float sg[3 * VOL];
        const int o = idx - NB_WH;
        if (t < VOL) vol[t] = weight_Rn[(size_t)o * VOL + t];
        if (t < 216) R[t]   = out_H[t];
        for (int i = t; i < 3 * VOL; i += 256) sg[i] = grid_Rn[i];
        __syncthreads();

#pragma unroll
        for (int f = t; f < N_OUT * VOL; f += 256) {
            const int b = f / VOL;
            const int p = f % VOL;
            const float* Rb = R + b * 9;

            const float g0 = sg[p], g1 = sg[VOL + p], g2 = sg[2 * VOL + p];
            float cz = Rb[0] * g0 + Rb[3] * g1 + Rb[6] * g2;
            float cy = Rb[1] * g0 + Rb[4] * g1 + Rb[7] * g2;
            float cx = Rb[2] * g0 + Rb[5] * g1 + Rb[8] * g2;
            cz = (cz + 1.f) * 0.5f * (KS - 1);
            cy = (cy + 1.f) * 0.5f * (KS - 1);
            cx = (cx + 1.f) * 0.5f * (KS - 1);

            const float z0f = floorf(cz), y0f = floorf(cy), x0f = floorf(cx);
            const int z0 = (int)z0f, y0 = (int)y0f, x0 = (int)x0f;
            const float fz = cz - z0f, fy = cy - y0f, fx = cx - x0f;

            float acc = 0.f;
#pragma unroll
            for (int dz = 0; dz < 2; dz++)
#pragma unroll
                for (int dy = 0; dy < 2; dy++)
#pragma unroll
                    for (int dx = 0; dx < 2; dx++) {
                        const int iz = z0 + dz, iy = y0 + dy, ix = x0 + dx;
                        const bool valid = (iz >= 0) & (iz < KS) & (iy >= 0) & (iy < KS)
                                         & (ix >= 0) & (ix < KS);
                        const int ci = min(max(iz, 0), KS - 1) * 25
                                     + min(max(iy, 0), KS - 1) * 5
                                     + min(max(ix, 0), KS - 1);
                        const float w = (dz ? fz : 1.f - fz) * (dy ? fy : 1.f - fy)
                                      * (dx ? fx : 1.f - fx);
                        acc += (valid ? vol[ci] : 0.f) * w;
                    }

            out[WH_SIZE + (size_t)o * (N_OUT * VOL) + f] = acc;
        }
    }
}

// ---------------------------------------------------------------------------
extern "C" void kernel_launch(void* const* d_in, const int* in_sizes, int n_in,
                              void* d_out, int out_size) {
    const float* in_H      = (const float*)d_in[0];
    const float* out_H     = (const float*)d_in[1];
    const float* grid_H    = (const float*)d_in[2];
    const float* grid_Rn   = (const float*)d_in[3];
    const float* weight_H  = (const float*)d_in[4];
    const float* weight_Rn = (const float*)d_in[5];
    float* out = (float*)d_out;

    fused_kernel<<<NB_WH + NB_RN, 256>>>(
        in_H, out_H, grid_H, grid_Rn, weight_H, weight_Rn, out);
}